// round 10
// baseline (speedup 1.0000x reference)
#include <cuda_runtime.h>
#include <math.h>

#define NN     100000
#define EE_MAX 3400000
#define HD     16
#define FIN    767
#define NC     10
#define EPSV   1e-12f

// ---------------- scratch ---------------------------------------------------
__device__ float g_hn  [NN * HD];   // normalized h
__device__ float g_nrm1[NN];        // max(||h||, eps)
__device__ float g_x1n [NN * HD];   // normalized x1
__device__ float g_nrm2[NN];        // max(||x1||, eps)
__device__ int   g_deg [NN];
__device__ int   g_rowptr[NN + 1];
__device__ int   g_cursor[NN];
__device__ int   g_csrc[EE_MAX];
__device__ int   g_aux[256];

// ---------------- f32x2 helpers ---------------------------------------------
__device__ __forceinline__ unsigned long long pk2(float lo, float hi) {
    unsigned long long r;
    asm("mov.b64 %0, {%1,%2};" : "=l"(r) : "f"(lo), "f"(hi));
    return r;
}
__device__ __forceinline__ void upk2(unsigned long long v, float& lo, float& hi) {
    asm("mov.b64 {%0,%1}, %2;" : "=f"(lo), "=f"(hi) : "l"(v));
}
__device__ __forceinline__ unsigned long long ffma2(unsigned long long a,
                                                    unsigned long long b,
                                                    unsigned long long c) {
    unsigned long long d;
    asm("fma.rn.f32x2 %0, %1, %2, %3;" : "=l"(d) : "l"(a), "l"(b), "l"(c));
    return d;
}
__device__ __forceinline__ unsigned long long fadd2(unsigned long long a,
                                                    unsigned long long b) {
    unsigned long long d;
    asm("add.rn.f32x2 %0, %1, %2;" : "=l"(d) : "l"(a), "l"(b));
    return d;
}

// ---------------- CSR build: 4 edges per thread ------------------------------
__global__ void k_count(const int* __restrict__ ei, int E, int n) {
    int idx = blockIdx.x * blockDim.x + threadIdx.x;
    int q = E >> 2, rem = E & 3;
    if (idx < q) {
        int4 d = __ldg((const int4*)(ei + E) + idx);
        atomicAdd(&g_deg[d.x], 1);
        atomicAdd(&g_deg[d.y], 1);
        atomicAdd(&g_deg[d.z], 1);
        atomicAdd(&g_deg[d.w], 1);
    } else if (idx < q + rem) {
        atomicAdd(&g_deg[__ldg(&ei[E + 4 * q + (idx - q)])], 1);
    } else if (idx < q + rem + n) {
        atomicAdd(&g_deg[idx - q - rem], 1);
    }
}

__global__ void k_scan_chunk(int n) {
    __shared__ int wsums[16];
    int tid = threadIdx.x, lane = tid & 31, w = tid >> 5;
    int gid = blockIdx.x * 512 + tid;
    int v = (gid < n) ? g_deg[gid] : 0;
    int s = v;
#pragma unroll
    for (int off = 1; off < 32; off <<= 1) {
        int t = __shfl_up_sync(0xffffffffu, s, off);
        if (lane >= off) s += t;
    }
    if (lane == 31) wsums[w] = s;
    __syncthreads();
    int add = 0;
#pragma unroll
    for (int i = 0; i < 16; i++) add += (i < w) ? wsums[i] : 0;
    s += add;
    if (gid < n) g_rowptr[gid + 1] = s;
    if (tid == 511) g_aux[blockIdx.x] = s;
}

__global__ __launch_bounds__(512) void k_scan_add(int n, int nchunk) {
    __shared__ int wsum[16];
    int tid = threadIdx.x, lane = tid & 31, w = tid >> 5;
    int b = blockIdx.x;
    int v = (tid < b && tid < nchunk) ? g_aux[tid] : 0;
#pragma unroll
    for (int off = 16; off; off >>= 1) v += __shfl_xor_sync(0xffffffffu, v, off);
    if (lane == 0) wsum[w] = v;
    __syncthreads();
    if (w == 0) {
        int t = (lane < 16) ? wsum[lane] : 0;
#pragma unroll
        for (int off = 8; off; off >>= 1) t += __shfl_xor_sync(0xffffffffu, t, off);
        if (lane == 0) wsum[0] = t;
    }
    __syncthreads();
    int offset = wsum[0];

    int gid = b * 512 + tid;
    if (gid < n) {
        int r = g_rowptr[gid + 1] + offset;
        g_rowptr[gid + 1] = r;
        if (gid + 1 < n) g_cursor[gid + 1] = r;
    }
    if (gid == 0) { g_rowptr[0] = 0; g_cursor[0] = 0; }
}

__global__ void k_scatter(const int* __restrict__ ei, int E, int n) {
    int idx = blockIdx.x * blockDim.x + threadIdx.x;
    int q = E >> 2, rem = E & 3;
    if (idx < q) {
        int4 s = __ldg((const int4*)ei + idx);
        int4 d = __ldg((const int4*)(ei + E) + idx);
        int p0 = atomicAdd(&g_cursor[d.x], 1);
        int p1 = atomicAdd(&g_cursor[d.y], 1);
        int p2 = atomicAdd(&g_cursor[d.z], 1);
        int p3 = atomicAdd(&g_cursor[d.w], 1);
        g_csrc[p0] = s.x;
        g_csrc[p1] = s.y;
        g_csrc[p2] = s.z;
        g_csrc[p3] = s.w;
    } else if (idx < q + rem) {
        int e = 4 * q + (idx - q);
        int pos = atomicAdd(&g_cursor[__ldg(&ei[E + e])], 1);
        g_csrc[pos] = __ldg(&ei[e]);
    } else if (idx < q + rem + n) {
        int v = idx - q - rem;
        int pos = atomicAdd(&g_cursor[v], 1);
        g_csrc[pos] = v;
    }
}

// ---------------- lin1: R4 shape (4 rows/warp, 8 kp/lane, j-span 32) ---------
#define LIN1_SMEM_BYTES (384 * 36 * 4)   // 55296
__global__ __launch_bounds__(256, 2) void k_lin1(const float* __restrict__ x,
                                                 const float* __restrict__ w,
                                                 const float* __restrict__ b,
                                                 float* __restrict__ hn,
                                                 float* __restrict__ nrm,
                                                 int n) {
    extern __shared__ float wf[];
    for (int q = threadIdx.x; q < 384 * 8; q += 256) {
        int jp = q >> 3, kp = q & 7;
        int j = 2 * jp, k = 2 * kp;
        float f0 = w[k * FIN + j];
        float f1 = w[(k + 1) * FIN + j];
        float f2 = (j + 1 < FIN) ? w[k * FIN + j + 1] : 0.f;
        float f3 = (j + 1 < FIN) ? w[(k + 1) * FIN + j + 1] : 0.f;
        *(float4*)(wf + jp * 36 + kp * 4) = make_float4(f0, f1, f2, f3);
    }
    __syncthreads();

    int warp = threadIdx.x >> 5, lane = threadIdx.x & 31;
    int rowBase = (blockIdx.x * 8 + warp) * 4;
    if (rowBase >= n) return;
    bool tailWarp = (rowBase + 4 >= n);

    unsigned long long acc[32];
#pragma unroll
    for (int i = 0; i < 32; i++) acc[i] = 0ull;

    const float* x0 = x + (size_t)rowBase * FIN;

    for (int it = 0; it < 12; ++it) {
        int jp = lane + it * 32;
        int j  = 2 * jp;
        unsigned long long alo[4], ahi[4];
#pragma unroll
        for (int r = 0; r < 4; r++) {
            const float* xr = x0 + r * FIN;
            float lo = xr[j];
            float hi = (tailWarp && jp == 383 && (rowBase + r) == n - 1)
                           ? 0.f : xr[j + 1];
            alo[r] = pk2(lo, lo);
            ahi[r] = pk2(hi, hi);
        }
#pragma unroll
        for (int kp = 0; kp < 8; kp++) {
            ulonglong2 wq = *(const ulonglong2*)(wf + jp * 36 + kp * 4);
#pragma unroll
            for (int r = 0; r < 4; r++) {
                unsigned long long a = acc[r * 8 + kp];
                a = ffma2(alo[r], wq.x, a);
                a = ffma2(ahi[r], wq.y, a);
                acc[r * 8 + kp] = a;
            }
        }
    }

#define REDSTEP(OFF, HALF)                                                     \
    {                                                                          \
        bool up = (lane & OFF) != 0;                                           \
        _Pragma("unroll")                                                      \
        for (int i = 0; i < HALF; i++) {                                       \
            unsigned long long send = up ? acc[i] : acc[i + HALF];             \
            unsigned long long recv = __shfl_xor_sync(0xffffffffu, send, OFF); \
            unsigned long long keep = up ? acc[i + HALF] : acc[i];             \
            acc[i] = fadd2(keep, recv);                                        \
        }                                                                      \
    }
    REDSTEP(16, 16)
    REDSTEP(8, 8)
    REDSTEP(4, 4)
    REDSTEP(2, 2)
    REDSTEP(1, 1)
#undef REDSTEP

    int r  = lane >> 3;
    int kk = (lane & 7) * 2;
    float h0, h1;
    upk2(acc[0], h0, h1);
    h0 = fmaxf(h0 + __ldg(b + kk),     0.f);
    h1 = fmaxf(h1 + __ldg(b + kk + 1), 0.f);
    float ss = h0 * h0 + h1 * h1;
    ss += __shfl_xor_sync(0xffffffffu, ss, 1);
    ss += __shfl_xor_sync(0xffffffffu, ss, 2);
    ss += __shfl_xor_sync(0xffffffffu, ss, 4);
    float nr  = fmaxf(sqrtf(ss), EPSV);
    float inv = 1.f / nr;
    int row = rowBase + r;
    float2 o; o.x = h0 * inv; o.y = h1 * inv;
    *(float2*)(hn + (size_t)row * HD + kk) = o;
    if ((lane & 7) == 0) nrm[row] = nr;
}

// ---------------- AGNN conv: compile-time gather bases (ALU diet) ------------
// MODE 0: gather g_hn/g_nrm1 ; out=x1(dptr), outn=g_x1n, nrmout=g_nrm2
// MODE 1: gather g_x1n/g_nrm2 ; out=log_softmax(lin2(h2))
template <int MODE>
__global__ __launch_bounds__(256) void k_conv(const float* __restrict__ beta_ptr,
                                              float* __restrict__ out,
                                              const float* __restrict__ w2,
                                              const float* __restrict__ b2,
                                              int n) {
    __shared__ float ws[NC * HD + NC];
    if (MODE == 1) {
        if (threadIdx.x < NC * HD) ws[threadIdx.x] = w2[threadIdx.x];
        if (threadIdx.x < NC)      ws[NC * HD + threadIdx.x] = b2[threadIdx.x];
        __syncthreads();
    }

    const float4* fn4        = (const float4*)(MODE == 0 ? g_hn : g_x1n);
    const float*  nrmT       = (MODE == 0 ? g_nrm1 : g_nrm2);

    int gw    = (blockIdx.x * blockDim.x + threadIdx.x) >> 5;
    int lane  = threadIdx.x & 31;
    if (gw >= n) return;
    int chunk = lane & 3;
    int slot  = lane >> 2;

    float beta = (MODE == 1) ? __ldg(beta_ptr) : 1.0f;
    float ab   = fabsf(beta);

    float4 q = fn4[gw * 4 + chunk];
    q.x *= beta; q.y *= beta; q.z *= beta; q.w *= beta;

    int start = g_rowptr[gw], end = g_rowptr[gw + 1];
    int nit = (end - start + 15) >> 4;

    float ssum = 0.f;
    float4 acc = make_float4(0.f, 0.f, 0.f, 0.f);

    int e0 = start + slot;
    bool v0 = (e0 < end),  v1 = (e0 + 8 < end);
    int s0 = v0 ? g_csrc[e0] : 0;
    int s1 = v1 ? g_csrc[e0 + 8] : 0;

    for (int it = 0; it < nit; ++it) {
        int  e2 = e0 + 16;
        bool v2 = (e2 < end), v3 = (e2 + 8 < end);
        int  s2 = v2 ? g_csrc[e2] : 0;
        int  s3 = v3 ? g_csrc[e2 + 8] : 0;
        float nv0 = nrmT[s0];
        float nv1 = nrmT[s1];
        float4 f0 = fn4[s0 * 4 + chunk];
        float4 f1 = fn4[s1 * 4 + chunk];
        float d0 = f0.x*q.x + f0.y*q.y + f0.z*q.z + f0.w*q.w;
        float d1 = f1.x*q.x + f1.y*q.y + f1.z*q.z + f1.w*q.w;
        d0 += __shfl_xor_sync(0xffffffffu, d0, 1);
        d1 += __shfl_xor_sync(0xffffffffu, d1, 1);
        d0 += __shfl_xor_sync(0xffffffffu, d0, 2);
        d1 += __shfl_xor_sync(0xffffffffu, d1, 2);
        float ex0 = v0 ? __expf(d0 - ab) : 0.f;
        float ex1 = v1 ? __expf(d1 - ab) : 0.f;
        float w0 = ex0 * nv0, w1 = ex1 * nv1;
        ssum += ex0 + ex1;
        acc.x += w0 * f0.x + w1 * f1.x;
        acc.y += w0 * f0.y + w1 * f1.y;
        acc.z += w0 * f0.z + w1 * f1.z;
        acc.w += w0 * f0.w + w1 * f1.w;
        e0 = e2; s0 = s2; s1 = s3; v0 = v2; v1 = v3;
    }

#pragma unroll
    for (int off = 4; off <= 16; off <<= 1) {
        ssum  += __shfl_xor_sync(0xffffffffu, ssum,  off);
        acc.x += __shfl_xor_sync(0xffffffffu, acc.x, off);
        acc.y += __shfl_xor_sync(0xffffffffu, acc.y, off);
        acc.z += __shfl_xor_sync(0xffffffffu, acc.z, off);
        acc.w += __shfl_xor_sync(0xffffffffu, acc.w, off);
    }
    float inv = 1.f / ssum;
    float4 o = make_float4(acc.x*inv, acc.y*inv, acc.z*inv, acc.w*inv);

    if (MODE == 0) {
        float ss = o.x*o.x + o.y*o.y + o.z*o.z + o.w*o.w;
        ss += __shfl_xor_sync(0xffffffffu, ss, 1);
        ss += __shfl_xor_sync(0xffffffffu, ss, 2);
        float nr   = fmaxf(sqrtf(ss), EPSV);
        float invn = 1.f / nr;
        if (slot == 0) {
            ((float4*)out)[gw * 4 + chunk] = o;
            ((float4*)g_x1n)[gw * 4 + chunk] =
                make_float4(o.x*invn, o.y*invn, o.z*invn, o.w*invn);
            if (lane == 0) g_nrm2[gw] = nr;
        }
    } else {
        float z[NC];
#pragma unroll
        for (int c = 0; c < NC; c++) {
            const float* wc = ws + c * HD + chunk * 4;
            z[c] = o.x*wc[0] + o.y*wc[1] + o.z*wc[2] + o.w*wc[3];
        }
#pragma unroll
        for (int off = 1; off <= 2; off <<= 1)
#pragma unroll
            for (int c = 0; c < NC; c++)
                z[c] += __shfl_xor_sync(0xffffffffu, z[c], off);
#pragma unroll
        for (int c = 0; c < NC; c++) z[c] += ws[NC * HD + c];
        float mx = z[0];
#pragma unroll
        for (int c = 1; c < NC; c++) mx = fmaxf(mx, z[c]);
        float se = 0.f;
#pragma unroll
        for (int c = 0; c < NC; c++) se += __expf(z[c] - mx);
        float lse = mx + __logf(se);
        if (lane < NC) out[gw * NC + lane] = z[lane] - lse;
    }
}

// ---------------- launch -----------------------------------------------------
extern "C" void kernel_launch(void* const* d_in, const int* in_sizes, int n_in,
                              void* d_out, int out_size) {
    const float* x    = (const float*)d_in[0];
    const int*   ei   = (const int*)  d_in[1];
    const float* w1   = (const float*)d_in[2];
    const float* b1   = (const float*)d_in[3];
    const float* bet2 = (const float*)d_in[4];
    const float* w2   = (const float*)d_in[5];
    const float* b2   = (const float*)d_in[6];
    float* out = (float*)d_out;

    int n = NN;
    int E = in_sizes[1] / 2;

    float* x1 = out + (size_t)n * NC;   // x1 output lives in d_out tail

    float* p_hn;  cudaGetSymbolAddress((void**)&p_hn,  g_hn);
    float* p_n1;  cudaGetSymbolAddress((void**)&p_n1,  g_nrm1);
    int*   p_deg; cudaGetSymbolAddress((void**)&p_deg, g_deg);

    static cudaStream_t s2 = nullptr;
    static cudaEvent_t evFork = nullptr, evJoin = nullptr;
    if (!s2) {
        cudaStreamCreateWithFlags(&s2, cudaStreamNonBlocking);
        cudaEventCreateWithFlags(&evFork, cudaEventDisableTiming);
        cudaEventCreateWithFlags(&evJoin, cudaEventDisableTiming);
        cudaFuncSetAttribute(k_lin1, cudaFuncAttributeMaxDynamicSharedMemorySize,
                             LIN1_SMEM_BYTES);
    }

    const int T = 256;
    int nchunk = (n + 511) / 512;
    int quarter = E >> 2, rem = E & 3;

    // ---- fork: CSR build on s2, lin1 on default stream ----
    cudaEventRecord(evFork, 0);
    cudaStreamWaitEvent(s2, evFork, 0);

    cudaMemsetAsync(p_deg, 0, n * sizeof(int), s2);
    // kernel #1
    k_count<<<(quarter + rem + n + T - 1) / T, T, 0, s2>>>(ei, E, n);
    // kernel #2
    k_scan_chunk<<<nchunk, 512, 0, s2>>>(n);
    // kernel #3
    k_scan_add<<<nchunk, 512, 0, s2>>>(n, nchunk);
    // kernel #4 (PROFILED): scatter
    k_scatter<<<(quarter + rem + n + T - 1) / T, T, 0, s2>>>(ei, E, n);

    // kernel #5: lin1 (main stream, concurrent with CSR chain)
    k_lin1<<<(n + 31) / 32, 256, LIN1_SMEM_BYTES>>>(x, w1, b1, p_hn, p_n1, n);

    // ---- join ----
    cudaEventRecord(evJoin, s2);
    cudaStreamWaitEvent(0, evJoin, 0);

    int convBlocks = (n * 32 + 255) / 256;
    // kernel #6: conv1
    k_conv<0><<<convBlocks, 256>>>(nullptr, x1, nullptr, nullptr, n);
    // kernel #7: conv2 (+ fused lin2/log_softmax)
    k_conv<1><<<convBlocks, 256>>>(bet2, out, w2, b2, n);
}

// round 11
// speedup vs baseline: 1.0233x; 1.0233x over previous
#include <cuda_runtime.h>
#include <math.h>

#define NN     100000
#define EE_MAX 3400000
#define HD     16
#define FIN    767
#define NC     10
#define EPSV   1e-12f

// ---------------- scratch ---------------------------------------------------
__device__ float g_hn  [NN * HD];   // normalized h
__device__ float g_nrm1[NN];        // max(||h||, eps)
__device__ float g_x1n [NN * HD];   // normalized x1
__device__ float g_nrm2[NN];        // max(||x1||, eps)
__device__ int   g_deg [NN];
__device__ int   g_rowptr[NN + 1];
__device__ int   g_cursor[NN];
__device__ int   g_csrc[EE_MAX];
__device__ int   g_aux[256];

// ---------------- f32x2 helpers ---------------------------------------------
__device__ __forceinline__ unsigned long long pk2(float lo, float hi) {
    unsigned long long r;
    asm("mov.b64 %0, {%1,%2};" : "=l"(r) : "f"(lo), "f"(hi));
    return r;
}
__device__ __forceinline__ void upk2(unsigned long long v, float& lo, float& hi) {
    asm("mov.b64 {%0,%1}, %2;" : "=f"(lo), "=f"(hi) : "l"(v));
}
__device__ __forceinline__ unsigned long long ffma2(unsigned long long a,
                                                    unsigned long long b,
                                                    unsigned long long c) {
    unsigned long long d;
    asm("fma.rn.f32x2 %0, %1, %2, %3;" : "=l"(d) : "l"(a), "l"(b), "l"(c));
    return d;
}
__device__ __forceinline__ unsigned long long fadd2(unsigned long long a,
                                                    unsigned long long b) {
    unsigned long long d;
    asm("add.rn.f32x2 %0, %1, %2;" : "=l"(d) : "l"(a), "l"(b));
    return d;
}

// ---------------- CSR build (int2 = measured best) ---------------------------
__global__ void k_count(const int* __restrict__ ei, int E, int n) {
    int idx = blockIdx.x * blockDim.x + threadIdx.x;
    int half = E >> 1;
    if (idx < half) {
        int2 d = __ldg((const int2*)(ei + E) + idx);
        atomicAdd(&g_deg[d.x], 1);
        atomicAdd(&g_deg[d.y], 1);
    } else if (idx < half + n) {
        atomicAdd(&g_deg[idx - half], 1);
    }
}

__global__ void k_scan_chunk(int n) {
    __shared__ int wsums[16];
    int tid = threadIdx.x, lane = tid & 31, w = tid >> 5;
    int gid = blockIdx.x * 512 + tid;
    int v = (gid < n) ? g_deg[gid] : 0;
    int s = v;
#pragma unroll
    for (int off = 1; off < 32; off <<= 1) {
        int t = __shfl_up_sync(0xffffffffu, s, off);
        if (lane >= off) s += t;
    }
    if (lane == 31) wsums[w] = s;
    __syncthreads();
    int add = 0;
#pragma unroll
    for (int i = 0; i < 16; i++) add += (i < w) ? wsums[i] : 0;
    s += add;
    if (gid < n) g_rowptr[gid + 1] = s;
    if (tid == 511) g_aux[blockIdx.x] = s;
}

__global__ __launch_bounds__(512) void k_scan_add(int n, int nchunk) {
    __shared__ int wsum[16];
    int tid = threadIdx.x, lane = tid & 31, w = tid >> 5;
    int b = blockIdx.x;
    int v = (tid < b && tid < nchunk) ? g_aux[tid] : 0;
#pragma unroll
    for (int off = 16; off; off >>= 1) v += __shfl_xor_sync(0xffffffffu, v, off);
    if (lane == 0) wsum[w] = v;
    __syncthreads();
    if (w == 0) {
        int t = (lane < 16) ? wsum[lane] : 0;
#pragma unroll
        for (int off = 8; off; off >>= 1) t += __shfl_xor_sync(0xffffffffu, t, off);
        if (lane == 0) wsum[0] = t;
    }
    __syncthreads();
    int offset = wsum[0];

    int gid = b * 512 + tid;
    if (gid < n) {
        int r = g_rowptr[gid + 1] + offset;
        g_rowptr[gid + 1] = r;
        if (gid + 1 < n) g_cursor[gid + 1] = r;
    }
    if (gid == 0) { g_rowptr[0] = 0; g_cursor[0] = 0; }
}

__global__ void k_scatter(const int* __restrict__ ei, int E, int n) {
    int idx = blockIdx.x * blockDim.x + threadIdx.x;
    int half = E >> 1;
    if (idx < half) {
        int2 s = __ldg((const int2*)ei + idx);
        int2 d = __ldg((const int2*)(ei + E) + idx);
        int p0 = atomicAdd(&g_cursor[d.x], 1);
        g_csrc[p0] = s.x;
        int p1 = atomicAdd(&g_cursor[d.y], 1);
        g_csrc[p1] = s.y;
    } else if (idx < half + n) {
        int v = idx - half;
        int pos = atomicAdd(&g_cursor[v], 1);
        g_csrc[pos] = v;
    }
}

// ---------------- lin1: R4 shape (4 rows/warp, 8 kp/lane, j-span 32) ---------
#define LIN1_SMEM_BYTES (384 * 36 * 4)   // 55296
__global__ __launch_bounds__(256, 2) void k_lin1(const float* __restrict__ x,
                                                 const float* __restrict__ w,
                                                 const float* __restrict__ b,
                                                 float* __restrict__ hn,
                                                 float* __restrict__ nrm,
                                                 int n) {
    extern __shared__ float wf[];
    for (int q = threadIdx.x; q < 384 * 8; q += 256) {
        int jp = q >> 3, kp = q & 7;
        int j = 2 * jp, k = 2 * kp;
        float f0 = w[k * FIN + j];
        float f1 = w[(k + 1) * FIN + j];
        float f2 = (j + 1 < FIN) ? w[k * FIN + j + 1] : 0.f;
        float f3 = (j + 1 < FIN) ? w[(k + 1) * FIN + j + 1] : 0.f;
        *(float4*)(wf + jp * 36 + kp * 4) = make_float4(f0, f1, f2, f3);
    }
    __syncthreads();

    int warp = threadIdx.x >> 5, lane = threadIdx.x & 31;
    int rowBase = (blockIdx.x * 8 + warp) * 4;
    if (rowBase >= n) return;
    bool tailWarp = (rowBase + 4 >= n);

    unsigned long long acc[32];
#pragma unroll
    for (int i = 0; i < 32; i++) acc[i] = 0ull;

    const float* x0 = x + (size_t)rowBase * FIN;

    for (int it = 0; it < 12; ++it) {
        int jp = lane + it * 32;
        int j  = 2 * jp;
        unsigned long long alo[4], ahi[4];
#pragma unroll
        for (int r = 0; r < 4; r++) {
            const float* xr = x0 + r * FIN;
            float lo = xr[j];
            float hi = (tailWarp && jp == 383 && (rowBase + r) == n - 1)
                           ? 0.f : xr[j + 1];
            alo[r] = pk2(lo, lo);
            ahi[r] = pk2(hi, hi);
        }
#pragma unroll
        for (int kp = 0; kp < 8; kp++) {
            ulonglong2 wq = *(const ulonglong2*)(wf + jp * 36 + kp * 4);
#pragma unroll
            for (int r = 0; r < 4; r++) {
                unsigned long long a = acc[r * 8 + kp];
                a = ffma2(alo[r], wq.x, a);
                a = ffma2(ahi[r], wq.y, a);
                acc[r * 8 + kp] = a;
            }
        }
    }

#define REDSTEP(OFF, HALF)                                                     \
    {                                                                          \
        bool up = (lane & OFF) != 0;                                           \
        _Pragma("unroll")                                                      \
        for (int i = 0; i < HALF; i++) {                                       \
            unsigned long long send = up ? acc[i] : acc[i + HALF];             \
            unsigned long long recv = __shfl_xor_sync(0xffffffffu, send, OFF); \
            unsigned long long keep = up ? acc[i + HALF] : acc[i];             \
            acc[i] = fadd2(keep, recv);                                        \
        }                                                                      \
    }
    REDSTEP(16, 16)
    REDSTEP(8, 8)
    REDSTEP(4, 4)
    REDSTEP(2, 2)
    REDSTEP(1, 1)
#undef REDSTEP

    int r  = lane >> 3;
    int kk = (lane & 7) * 2;
    float h0, h1;
    upk2(acc[0], h0, h1);
    h0 = fmaxf(h0 + __ldg(b + kk),     0.f);
    h1 = fmaxf(h1 + __ldg(b + kk + 1), 0.f);
    float ss = h0 * h0 + h1 * h1;
    ss += __shfl_xor_sync(0xffffffffu, ss, 1);
    ss += __shfl_xor_sync(0xffffffffu, ss, 2);
    ss += __shfl_xor_sync(0xffffffffu, ss, 4);
    float nr  = fmaxf(sqrtf(ss), EPSV);
    float inv = 1.f / nr;
    int row = rowBase + r;
    float2 o; o.x = h0 * inv; o.y = h1 * inv;
    *(float2*)(hn + (size_t)row * HD + kk) = o;
    if ((lane & 7) == 0) nrm[row] = nr;
}

// ---------------- AGNN conv: compile-time bases + __ldg + clamped loads ------
template <int MODE>
__global__ __launch_bounds__(256) void k_conv(const float* __restrict__ beta_ptr,
                                              float* __restrict__ out,
                                              const float* __restrict__ w2,
                                              const float* __restrict__ b2,
                                              int n) {
    __shared__ float ws[NC * HD + NC];
    if (MODE == 1) {
        if (threadIdx.x < NC * HD) ws[threadIdx.x] = w2[threadIdx.x];
        if (threadIdx.x < NC)      ws[NC * HD + threadIdx.x] = b2[threadIdx.x];
        __syncthreads();
    }

    const float4* fn4  = (const float4*)(MODE == 0 ? g_hn : g_x1n);
    const float*  nrmT = (MODE == 0 ? g_nrm1 : g_nrm2);

    int gw    = (blockIdx.x * blockDim.x + threadIdx.x) >> 5;
    int lane  = threadIdx.x & 31;
    if (gw >= n) return;
    int chunk = lane & 3;
    int slot  = lane >> 2;

    float beta = (MODE == 1) ? __ldg(beta_ptr) : 1.0f;
    float ab   = fabsf(beta);

    float4 q = __ldg(fn4 + gw * 4 + chunk);
    q.x *= beta; q.y *= beta; q.z *= beta; q.w *= beta;

    int start = __ldg(&g_rowptr[gw]), end = __ldg(&g_rowptr[gw + 1]);
    int last  = end - 1;
    int nit = (end - start + 15) >> 4;

    float ssum = 0.f;
    float4 acc = make_float4(0.f, 0.f, 0.f, 0.f);

    int e0 = start + slot;
    bool v0 = (e0 < end),  v1 = (e0 + 8 < end);
    int s0 = __ldg(&g_csrc[min(e0, last)]);
    int s1 = __ldg(&g_csrc[min(e0 + 8, last)]);

    for (int it = 0; it < nit; ++it) {
        int  e2 = e0 + 16;
        bool v2 = (e2 < end), v3 = (e2 + 8 < end);
        int  s2 = __ldg(&g_csrc[min(e2, last)]);
        int  s3 = __ldg(&g_csrc[min(e2 + 8, last)]);
        float nv0 = __ldg(&nrmT[s0]);
        float nv1 = __ldg(&nrmT[s1]);
        float4 f0 = __ldg(fn4 + s0 * 4 + chunk);
        float4 f1 = __ldg(fn4 + s1 * 4 + chunk);
        float d0 = f0.x*q.x + f0.y*q.y + f0.z*q.z + f0.w*q.w;
        float d1 = f1.x*q.x + f1.y*q.y + f1.z*q.z + f1.w*q.w;
        d0 += __shfl_xor_sync(0xffffffffu, d0, 1);
        d1 += __shfl_xor_sync(0xffffffffu, d1, 1);
        d0 += __shfl_xor_sync(0xffffffffu, d0, 2);
        d1 += __shfl_xor_sync(0xffffffffu, d1, 2);
        float ex0 = v0 ? __expf(d0 - ab) : 0.f;
        float ex1 = v1 ? __expf(d1 - ab) : 0.f;
        float w0 = ex0 * nv0, w1 = ex1 * nv1;
        ssum += ex0 + ex1;
        acc.x += w0 * f0.x + w1 * f1.x;
        acc.y += w0 * f0.y + w1 * f1.y;
        acc.z += w0 * f0.z + w1 * f1.z;
        acc.w += w0 * f0.w + w1 * f1.w;
        e0 = e2; s0 = s2; s1 = s3; v0 = v2; v1 = v3;
    }

#pragma unroll
    for (int off = 4; off <= 16; off <<= 1) {
        ssum  += __shfl_xor_sync(0xffffffffu, ssum,  off);
        acc.x += __shfl_xor_sync(0xffffffffu, acc.x, off);
        acc.y += __shfl_xor_sync(0xffffffffu, acc.y, off);
        acc.z += __shfl_xor_sync(0xffffffffu, acc.z, off);
        acc.w += __shfl_xor_sync(0xffffffffu, acc.w, off);
    }
    float inv = 1.f / ssum;
    float4 o = make_float4(acc.x*inv, acc.y*inv, acc.z*inv, acc.w*inv);

    if (MODE == 0) {
        float ss = o.x*o.x + o.y*o.y + o.z*o.z + o.w*o.w;
        ss += __shfl_xor_sync(0xffffffffu, ss, 1);
        ss += __shfl_xor_sync(0xffffffffu, ss, 2);
        float nr   = fmaxf(sqrtf(ss), EPSV);
        float invn = 1.f / nr;
        if (slot == 0) {
            ((float4*)out)[gw * 4 + chunk] = o;
            ((float4*)g_x1n)[gw * 4 + chunk] =
                make_float4(o.x*invn, o.y*invn, o.z*invn, o.w*invn);
            if (lane == 0) g_nrm2[gw] = nr;
        }
    } else {
        float z[NC];
#pragma unroll
        for (int c = 0; c < NC; c++) {
            const float* wc = ws + c * HD + chunk * 4;
            z[c] = o.x*wc[0] + o.y*wc[1] + o.z*wc[2] + o.w*wc[3];
        }
#pragma unroll
        for (int off = 1; off <= 2; off <<= 1)
#pragma unroll
            for (int c = 0; c < NC; c++)
                z[c] += __shfl_xor_sync(0xffffffffu, z[c], off);
#pragma unroll
        for (int c = 0; c < NC; c++) z[c] += ws[NC * HD + c];
        float mx = z[0];
#pragma unroll
        for (int c = 1; c < NC; c++) mx = fmaxf(mx, z[c]);
        float se = 0.f;
#pragma unroll
        for (int c = 0; c < NC; c++) se += __expf(z[c] - mx);
        float lse = mx + __logf(se);
        if (lane < NC) out[gw * NC + lane] = z[lane] - lse;
    }
}

// ---------------- launch -----------------------------------------------------
extern "C" void kernel_launch(void* const* d_in, const int* in_sizes, int n_in,
                              void* d_out, int out_size) {
    const float* x    = (const float*)d_in[0];
    const int*   ei   = (const int*)  d_in[1];
    const float* w1   = (const float*)d_in[2];
    const float* b1   = (const float*)d_in[3];
    const float* bet2 = (const float*)d_in[4];
    const float* w2   = (const float*)d_in[5];
    const float* b2   = (const float*)d_in[6];
    float* out = (float*)d_out;

    int n = NN;
    int E = in_sizes[1] / 2;

    float* x1 = out + (size_t)n * NC;   // x1 output lives in d_out tail

    float* p_hn;  cudaGetSymbolAddress((void**)&p_hn,  g_hn);
    float* p_n1;  cudaGetSymbolAddress((void**)&p_n1,  g_nrm1);
    int*   p_deg; cudaGetSymbolAddress((void**)&p_deg, g_deg);

    static cudaStream_t sMain = nullptr, s2 = nullptr;
    static cudaEvent_t evFork = nullptr, evJoinA = nullptr, evJoinB = nullptr;
    if (!s2) {
        int loPri, hiPri;
        cudaDeviceGetStreamPriorityRange(&loPri, &hiPri);
        cudaStreamCreateWithPriority(&sMain, cudaStreamNonBlocking, hiPri);
        cudaStreamCreateWithPriority(&s2,    cudaStreamNonBlocking, loPri);
        cudaEventCreateWithFlags(&evFork,  cudaEventDisableTiming);
        cudaEventCreateWithFlags(&evJoinA, cudaEventDisableTiming);
        cudaEventCreateWithFlags(&evJoinB, cudaEventDisableTiming);
        cudaFuncSetAttribute(k_lin1, cudaFuncAttributeMaxDynamicSharedMemorySize,
                             LIN1_SMEM_BYTES);
    }

    const int T = 256;
    int nchunk = (n + 511) / 512;
    int half = E >> 1;

    // ---- fork: CSR build on s2 (low pri), lin1 on sMain (high pri) ----
    cudaEventRecord(evFork, 0);
    cudaStreamWaitEvent(s2, evFork, 0);
    cudaStreamWaitEvent(sMain, evFork, 0);

    cudaMemsetAsync(p_deg, 0, n * sizeof(int), s2);
    // kernel #1
    k_count<<<(half + n + T - 1) / T, T, 0, s2>>>(ei, E, n);
    // kernel #2
    k_scan_chunk<<<nchunk, 512, 0, s2>>>(n);
    // kernel #3
    k_scan_add<<<nchunk, 512, 0, s2>>>(n, nchunk);
    // kernel #4 (PROFILED): scatter
    k_scatter<<<(half + n + T - 1) / T, T, 0, s2>>>(ei, E, n);

    // kernel #5: lin1 (high-priority stream, concurrent with CSR chain)
    k_lin1<<<(n + 31) / 32, 256, LIN1_SMEM_BYTES, sMain>>>(x, w1, b1, p_hn, p_n1, n);

    // ---- join back onto capture stream ----
    cudaEventRecord(evJoinA, s2);
    cudaEventRecord(evJoinB, sMain);
    cudaStreamWaitEvent(0, evJoinA, 0);
    cudaStreamWaitEvent(0, evJoinB, 0);

    int convBlocks = (n * 32 + 255) / 256;
    // kernel #6: conv1
    k_conv<0><<<convBlocks, 256>>>(nullptr, x1, nullptr, nullptr, n);
    // kernel #7: conv2 (+ fused lin2/log_softmax)
    k_conv<1><<<convBlocks, 256>>>(bet2, out, w2, b2, n);
}